// round 10
// baseline (speedup 1.0000x reference)
#include <cuda_runtime.h>
#include <cuda_fp16.h>
#include <cstdint>

// Sizes
#define BSZ 512
#define HID 1024
#define NG  4096
#define INP 128
#define SEQ 96
#define NCTA 128           // persistent grid: 2 mtiles x 64 ntiles
#define KCH 16             // K chunks of 64 halfs
#define ATILEH 16384       // halfs per A chunk tile (256 x 64)
#define ATILEB 32768       // bytes per A chunk tile
#define BTILEB 8192        // bytes per B chunk tile (64 x 64 halfs)
#define SM_B 0             // B panel at smem offset 0 (16 x 8192 = 131072)
#define SM_A 131072        // A stages / C staging union
#define SMEM_BYTES (131072 + 3 * ATILEB)   // 229376

// Scratch (__device__ globals; no cudaMalloc allowed)
__device__ __align__(128) __half d_Weff[(size_t)NG * HID];     // [ntile*16+ch][64][64] swizzled
__device__ float d_beff[NG];                                   // permuted linear
__device__ float d_D0[(size_t)BSZ * NG];                       // step-0 correction [b][n']
__device__ float d_u0[BSZ * INP];
__device__ __align__(128) __half d_hbuf[2][(size_t)BSZ * HID]; // [mtile*16+ch][256][64] swizzled
__device__ float d_part[(size_t)SEQ * 64 * BSZ];               // [t][ntile][b]
__device__ unsigned d_flag[SEQ * 2 * KCH];                     // [t][mtile][chunk] producer count

__device__ __forceinline__ float sigm(float x) { return 1.0f / (1.0f + __expf(-x)); }
__device__ __forceinline__ float tanhe(float x) {
    x = fminf(fmaxf(x, -15.f), 15.f);
    float e = __expf(-2.f * x);
    return (1.f - e) / (1.f + e);
}
__device__ __forceinline__ int permrow(int np) { return ((np & 3) << 10) | (np >> 2); }
__device__ __forceinline__ uint32_t sw128(uint32_t o) { return o ^ ((o >> 3) & 0x70); }

__device__ __forceinline__ uint32_t s2u(const void* p) {
    uint32_t a;
    asm("{ .reg .u64 t; cvta.to.shared.u64 t, %1; cvt.u32.u64 %0, t; }" : "=r"(a) : "l"(p));
    return a;
}
__device__ __forceinline__ void bulkcp(uint32_t dst, const void* src, uint32_t bytes, uint32_t mbar) {
    asm volatile(
        "cp.async.bulk.shared::cluster.global.mbarrier::complete_tx::bytes [%0], [%1], %2, [%3];"
        :: "r"(dst), "l"(src), "r"(bytes), "r"(mbar) : "memory");
}
__device__ __forceinline__ void mma16(float* c, const unsigned* a, const unsigned* b) {
    asm volatile(
        "mma.sync.aligned.m16n8k16.row.col.f32.f16.f16.f32 "
        "{%0,%1,%2,%3}, {%4,%5,%6,%7}, {%8,%9}, {%0,%1,%2,%3};"
        : "+f"(c[0]), "+f"(c[1]), "+f"(c[2]), "+f"(c[3])
        : "r"(a[0]), "r"(a[1]), "r"(a[2]), "r"(a[3]), "r"(b[0]), "r"(b[1]));
}
__device__ __forceinline__ unsigned pack_h2(float a, float b) {
    unsigned lo = (unsigned)__half_as_ushort(__float2half_rn(a));
    unsigned hi = (unsigned)__half_as_ushort(__float2half_rn(b));
    return lo | (hi << 16);
}
#define MBINIT(a, n) \
    asm volatile("mbarrier.init.shared.b64 [%0], %1;" :: "r"(a), "r"(n) : "memory")
#define MBEXPECT(a, n) \
    asm volatile("mbarrier.arrive.expect_tx.shared.b64 _, [%0], %1;" :: "r"(a), "r"(n) : "memory")
#define MBWAIT(a, ph) \
    asm volatile("{\n\t.reg .pred P;\n\tWL_%=: mbarrier.try_wait.parity.acquire.cta.shared::cta.b64 P, [%0], %1, 0x989680;\n\t@P bra.uni WD_%=;\n\tbra.uni WL_%=;\n\tWD_%=:\n\t}" \
                 :: "r"(a), "r"((uint32_t)(ph)) : "memory")
#define FPROXY() asm volatile("fence.proxy.async.shared::cta;" ::: "memory")
#define FPROXY_ALL() asm volatile("fence.proxy.async;" ::: "memory")

// ---------------- Precompute kernels ----------------

__global__ void k_rst() {
    int i = blockIdx.x * 256 + threadIdx.x;
    if (i < SEQ * 2 * KCH) d_flag[i] = 0u;
}

// W_eff[n'][m] = W_hh[r][m] + sum_k W_ih[r][k]*W_fc[k][m]; store to B tile layout fp16
__global__ void k_weff(const float* __restrict__ Wih, const float* __restrict__ Whh,
                       const float* __restrict__ Wfc) {
    __shared__ float wih_s[4][INP];
    int m = blockIdx.x * 256 + threadIdx.x;   // grid.x = 4
    int npb = blockIdx.y * 4;                 // grid.y = 1024
    for (int idx = threadIdx.x; idx < 4 * INP; idx += 256)
        wih_s[idx >> 7][idx & 127] = Wih[permrow(npb + (idx >> 7)) * INP + (idx & 127)];
    __syncthreads();
    float acc[4];
    #pragma unroll
    for (int i = 0; i < 4; i++) acc[i] = Whh[(size_t)permrow(npb + i) * HID + m];
    for (int k = 0; k < INP; k++) {
        float w = Wfc[k * HID + m];
        #pragma unroll
        for (int i = 0; i < 4; i++) acc[i] += wih_s[i][k] * w;
    }
    int chunk = m >> 6, kc = m & 63;
    #pragma unroll
    for (int i = 0; i < 4; i++) {
        int np = npb + i;
        int tile = (np >> 6) * 16 + chunk;
        uint32_t bo = sw128((uint32_t)((np & 63) * 128 + kc * 2));
        *(__half*)((char*)d_Weff + (size_t)tile * BTILEB + bo) = __float2half_rn(acc[i]);
    }
}

// h0 (fp16, A tile layout)
__global__ void k_state(const float* __restrict__ hid) {
    int i = blockIdx.x * 256 + threadIdx.x;   // grid 2048
    int b = i >> 10, j = i & 1023;
    int tile = (b >> 8) * 16 + (j >> 6);
    uint32_t bo = sw128((uint32_t)((b & 255) * 128 + (j & 63) * 2));
    *(__half*)((char*)d_hbuf[0] + (size_t)tile * ATILEB + bo) = __float2half_rn(hid[i]);
}

// u0[b][k] = x0[b][k] - b_fc[k] - h0[b]·W_fc[k]
__global__ void k_u0(const float* __restrict__ xt, const float* __restrict__ hid,
                     const float* __restrict__ Wfc, const float* __restrict__ bfc) {
    __shared__ float hs[HID];
    int b = blockIdx.x, k = threadIdx.x;
    for (int i = k; i < HID; i += 128) hs[i] = hid[b * HID + i];
    __syncthreads();
    float acc = 0.f;
    const float* w = Wfc + k * HID;
    for (int i = 0; i < HID; i++) acc += hs[i] * w[i];
    d_u0[b * INP + k] = xt[b * INP + k] - bfc[k] - acc;
}

// b_eff[n'] = b_ih[r]+b_hh[r]+W_ih[r]·b_fc
__global__ void k_beff(const float* __restrict__ Wih, const float* __restrict__ bih,
                       const float* __restrict__ bhh, const float* __restrict__ bfc) {
    int np = blockIdx.x * 256 + threadIdx.x;
    int r = permrow(np);
    float acc = bih[r] + bhh[r];
    for (int k = 0; k < INP; k++) acc += Wih[r * INP + k] * bfc[k];
    d_beff[np] = acc;
}

// D0[b][n'] = u0[b]·W_ih[r]
__global__ void k_d0(const float* __restrict__ Wih) {
    __shared__ float us[4][INP];
    int tid = threadIdx.x;
    int bq = blockIdx.y;
    int np = blockIdx.x * 128 + tid;
    #pragma unroll
    for (int i = 0; i < 4; i++) us[i][tid] = d_u0[(bq * 4 + i) * INP + tid];
    __syncthreads();
    int r = permrow(np);
    float a0 = 0, a1 = 0, a2 = 0, a3 = 0;
    for (int k = 0; k < INP; k++) {
        float w = Wih[r * INP + k];
        a0 += us[0][k] * w; a1 += us[1][k] * w; a2 += us[2][k] * w; a3 += us[3][k] * w;
    }
    d_D0[(size_t)(bq * 4 + 0) * NG + np] = a0;
    d_D0[(size_t)(bq * 4 + 1) * NG + np] = a1;
    d_D0[(size_t)(bq * 4 + 2) * NG + np] = a2;
    d_D0[(size_t)(bq * 4 + 3) * NG + np] = a3;
}

// ---------------- Persistent kernel: all 96 steps, flag-based dataflow ----------------
__global__ void __launch_bounds__(256, 1)
k_lstm(const float* __restrict__ cell, const float* __restrict__ Wfc) {
    extern __shared__ char smem[];
    __shared__ __align__(8) unsigned long long mb[4];   // 0..2 A stages, 3 = B
    __shared__ float s_beff[64];
    __shared__ float s_w127[16];

    const int tid = threadIdx.x, lane = tid & 31, wid = tid >> 5;
    const int wm = wid & 3, wn = wid >> 2;        // 4 x 2 warp grid (64M x 32N)
    const int gid = lane >> 2, tig = lane & 3;
    const int cta = blockIdx.x;
    const int mtile = cta >> 6, ntile = cta & 63;
    const int m0 = mtile * 256;

    if (tid < 64) s_beff[tid] = d_beff[ntile * 64 + tid];
    if (tid < 16) s_w127[tid] = Wfc[127 * HID + ntile * 16 + tid];
    if (tid == 0) {
        #pragma unroll
        for (int s = 0; s < 4; s++) MBINIT(s2u(&mb[s]), 1);
        FPROXY();
    }
    __syncthreads();

    // Load resident B panel (128 KB, once)
    if (tid == 0) {
        MBEXPECT(s2u(&mb[3]), 16 * BTILEB);
        bulkcp(s2u(smem + SM_B), d_Weff + (size_t)ntile * 16 * (BTILEB / 2), 16 * BTILEB,
               s2u(&mb[3]));
    }

    // c state in registers (thread = batch row m0+tid, units ntile*16 .. +15)
    float creg[16];
    {
        const float4* cp = (const float4*)(cell + (size_t)(m0 + tid) * HID + ntile * 16);
        #pragma unroll
        for (int q = 0; q < 4; q++) {
            float4 v = cp[q];
            creg[q * 4 + 0] = v.x; creg[q * 4 + 1] = v.y;
            creg[q * 4 + 2] = v.z; creg[q * 4 + 3] = v.w;
        }
    }
    MBWAIT(s2u(&mb[3]), 0);

    float* smC = (float*)(smem + SM_A);    // C staging overlaps A stages (between steps)

    int issued = 0;     // next global chunk index to issue (tid0 state; chunk cc = t*16+c)

    // tid0-only: issue bulk copies for chunks [issued, target), gated on producer flags.
    // blocking=true spins on the flag; otherwise stops at first not-ready chunk.
    auto issue_upto = [&](int target, bool blocking) {
        while (issued < target) {
            int it = issued >> 4, ic = issued & 15;
            if (it > 0) {
                volatile unsigned* f = &d_flag[(it * 2 + mtile) * KCH + ic];
                if (*f < 4u) {
                    if (!blocking) return;
                    while (*f < 4u) { }
                }
                __threadfence();
            }
            int s = issued % 3;
            MBEXPECT(s2u(&mb[s]), ATILEB);
            bulkcp(s2u(smem + SM_A + s * ATILEB),
                   d_hbuf[it & 1] + (size_t)(mtile * 16 + ic) * ATILEH,
                   ATILEB, s2u(&mb[s]));
            issued++;
        }
    };

    for (int t = 0; t < SEQ; t++) {
        const int tlimit = (t + 1) * KCH;   // no cross-step prefetch (C-dump reuses stage smem)

        float acc[4][4][4];
        #pragma unroll
        for (int a = 0; a < 4; a++)
            #pragma unroll
            for (int b = 0; b < 4; b++)
                #pragma unroll
                for (int c = 0; c < 4; c++) acc[a][b][c] = 0.f;

        for (int c = 0; c < KCH; c++) {
            const int cc = t * KCH + c;
            if (tid == 0) {
                issue_upto(cc + 1, true);                       // ensure current chunk in flight
                int tg = cc + 3; if (tg > tlimit) tg = tlimit;
                issue_upto(tg, false);                          // opportunistic lookahead
            }
            const int s = cc % 3;
            MBWAIT(s2u(&mb[s]), (cc / 3) & 1);

            const unsigned* As = (const unsigned*)(smem + SM_A + s * ATILEB);
            const unsigned* Bs = (const unsigned*)(smem + SM_B + c * BTILEB);
            #pragma unroll
            for (int k8 = 0; k8 < 32; k8 += 8) {
                unsigned a[4][4], b[4][2];
                #pragma unroll
                for (int mf = 0; mf < 4; mf++) {
                    int r = wm * 64 + mf * 16 + gid;
                    int xr = (r & 7) << 2;
                    int c0 = (k8 + tig) ^ xr, c1 = (k8 + tig + 4) ^ xr;
                    a[mf][0] = As[r * 32 + c0];
                    a[mf][1] = As[(r + 8) * 32 + c0];
                    a[mf][2] = As[r * 32 + c1];
                    a[mf][3] = As[(r + 8) * 32 + c1];
                }
                #pragma unroll
                for (int nf = 0; nf < 4; nf++) {
                    int n = wn * 32 + nf * 8 + gid;
                    int xn = (n & 7) << 2;
                    b[nf][0] = Bs[n * 32 + ((k8 + tig) ^ xn)];
                    b[nf][1] = Bs[n * 32 + ((k8 + tig + 4) ^ xn)];
                }
                #pragma unroll
                for (int mf = 0; mf < 4; mf++)
                    #pragma unroll
                    for (int nf = 0; nf < 4; nf++) mma16(acc[mf][nf], a[mf], b[nf]);
            }
            __syncthreads();   // stage s free for reuse after this
        }

        // dump C tile (256 x 64, stride 66) — overlaps stage smem, safe: no cross-step prefetch
        #pragma unroll
        for (int mf = 0; mf < 4; mf++)
            #pragma unroll
            for (int nf = 0; nf < 4; nf++) {
                int row = wm * 64 + mf * 16 + gid;
                int col = wn * 32 + nf * 8 + 2 * tig;
                *(float2*)&smC[row * 66 + col]       = make_float2(acc[mf][nf][0], acc[mf][nf][1]);
                *(float2*)&smC[(row + 8) * 66 + col] = make_float2(acc[mf][nf][2], acc[mf][nf][3]);
            }
        __syncthreads();

        // fused LSTM epilogue: thread = batch row
        {
            const float* myc = smC + tid * 66;
            const float4* d0p = (const float4*)(d_D0 + (size_t)(m0 + tid) * NG + ntile * 64);
            const bool is0 = (t == 0);
            float part = 0.f;
            unsigned hp[8];
            #pragma unroll
            for (int u2 = 0; u2 < 8; u2++) {
                float hv2[2];
                #pragma unroll
                for (int v = 0; v < 2; v++) {
                    int u = u2 * 2 + v;
                    float2 p0 = *(const float2*)(myc + 4 * u);
                    float2 p1 = *(const float2*)(myc + 4 * u + 2);
                    float gi = p0.x + s_beff[4 * u];
                    float gf = p0.y + s_beff[4 * u + 1];
                    float gg = p1.x + s_beff[4 * u + 2];
                    float go = p1.y + s_beff[4 * u + 3];
                    if (is0) {
                        float4 dd = d0p[u];
                        gi += dd.x; gf += dd.y; gg += dd.z; go += dd.w;
                    }
                    float cn = sigm(gf) * creg[u] + sigm(gi) * tanhe(gg);
                    float hv = sigm(go) * tanhe(cn);
                    creg[u] = cn;
                    part += hv * s_w127[u];
                    hv2[v] = hv;
                }
                hp[u2] = pack_h2(hv2[0], hv2[1]);
            }
            // h -> next-step A layout (fp16 swizzled; second 16B block at sw ^ 16)
            char* hT = (char*)(d_hbuf[(t + 1) & 1]) + (size_t)(mtile * 16 + (ntile >> 2)) * ATILEB;
            uint32_t bo = (uint32_t)(tid * 128 + (ntile & 3) * 32);
            uint32_t sw = bo ^ ((bo >> 3) & 0x70);
            *(uint4*)(hT + sw)        = make_uint4(hp[0], hp[1], hp[2], hp[3]);
            *(uint4*)(hT + (sw ^ 16)) = make_uint4(hp[4], hp[5], hp[6], hp[7]);
            d_part[((size_t)t * 64 + ntile) * BSZ + m0 + tid] = part;
        }

        // publish h stores, then raise this CTA's producer flag for step t+1
        __syncthreads();
        if (tid == 0 && t + 1 < SEQ) {
            __threadfence();
            FPROXY_ALL();
            atomicAdd(&d_flag[((t + 1) * 2 + mtile) * KCH + (ntile >> 2)], 1u);
        }
    }
}

// out[b][t] = b_fc[127] + sum over 64 tiles
__global__ void k_reduce(float* __restrict__ out, const float* __restrict__ bfc) {
    int idx = blockIdx.x * 256 + threadIdx.x;
    if (idx >= BSZ * SEQ) return;
    int b = idx / SEQ, t = idx % SEQ;
    float s = bfc[127];
    #pragma unroll 8
    for (int nt = 0; nt < 64; nt++) s += d_part[((size_t)t * 64 + nt) * BSZ + b];
    out[idx] = s;
}

extern "C" void kernel_launch(void* const* d_in, const int* in_sizes, int n_in,
                              void* d_out, int out_size) {
    const float* xt   = (const float*)d_in[0];
    const float* hid  = (const float*)d_in[1];
    const float* cell = (const float*)d_in[2];
    const float* Wih  = (const float*)d_in[3];
    const float* Whh  = (const float*)d_in[4];
    const float* bih  = (const float*)d_in[5];
    const float* bhh  = (const float*)d_in[6];
    const float* Wfc  = (const float*)d_in[7];
    const float* bfc  = (const float*)d_in[8];
    float* out = (float*)d_out;

    cudaFuncSetAttribute(k_lstm, cudaFuncAttributeMaxDynamicSharedMemorySize, SMEM_BYTES);

    k_rst<<<12, 256>>>();
    k_weff<<<dim3(4, 1024), 256>>>(Wih, Whh, Wfc);
    k_state<<<2048, 256>>>(hid);
    k_u0<<<512, 128>>>(xt, hid, Wfc, bfc);
    k_beff<<<16, 256>>>(Wih, bih, bhh, bfc);
    k_d0<<<dim3(32, 128), 128>>>(Wih);
    k_lstm<<<NCTA, 256, SMEM_BYTES>>>(cell, Wfc);
    k_reduce<<<192, 256>>>(out, bfc);
}

// round 11
// speedup vs baseline: 1.5149x; 1.5149x over previous
#include <cuda_runtime.h>
#include <cuda_fp16.h>
#include <cstdint>

// Sizes
#define BSZ 512
#define HID 1024
#define NG  4096
#define INP 128
#define SEQ 96
#define NCH 16             // K chunks of 64 halfs
#define TILEHF 8192        // halfs per 128x64 tile
#define TILEB 16384        // bytes per tile (128 rows x 128 B)
#define STG 4              // pipeline stages
#define SMEM_BYTES (STG * 2 * TILEB)   // 131072 dynamic

// Scratch (__device__ globals; no cudaMalloc allowed)
__device__ __align__(128) __half d_Weff[(size_t)NG * HID];    // tiled+swizzled [ntile*16+ch][128][64]
__device__ float d_beff[NG];                                  // permuted linear
__device__ float d_D0[(size_t)BSZ * NG];                      // step-0 correction [b][n']
__device__ float d_u0[BSZ * INP];
__device__ __align__(128) __half d_hbuf[2][(size_t)BSZ * HID]; // tiled+swizzled [mtile*16+ch][128][64]
__device__ float d_cbuf[(size_t)BSZ * HID];                   // linear [b][j]
__device__ float d_part[(size_t)SEQ * 32 * BSZ];

__device__ __forceinline__ float sigm(float x) { return 1.0f / (1.0f + __expf(-x)); }
__device__ __forceinline__ int permrow(int np) { return ((np & 3) << 10) | (np >> 2); }
__device__ __forceinline__ uint32_t sw128(uint32_t o) { return o ^ ((o >> 3) & 0x70); }

__device__ __forceinline__ uint32_t s2u(const void* p) {
    uint32_t a;
    asm("{ .reg .u64 t; cvta.to.shared.u64 t, %1; cvt.u32.u64 %0, t; }" : "=r"(a) : "l"(p));
    return a;
}
__device__ __forceinline__ void bulkcp(uint32_t dst, const void* src, uint32_t bytes, uint32_t mbar) {
    asm volatile(
        "cp.async.bulk.shared::cluster.global.mbarrier::complete_tx::bytes [%0], [%1], %2, [%3];"
        :: "r"(dst), "l"(src), "r"(bytes), "r"(mbar) : "memory");
}
__device__ __forceinline__ void mma16(float* c, const unsigned* a, const unsigned* b) {
    asm volatile(
        "mma.sync.aligned.m16n8k16.row.col.f32.f16.f16.f32 "
        "{%0,%1,%2,%3}, {%4,%5,%6,%7}, {%8,%9}, {%0,%1,%2,%3};"
        : "+f"(c[0]), "+f"(c[1]), "+f"(c[2]), "+f"(c[3])
        : "r"(a[0]), "r"(a[1]), "r"(a[2]), "r"(a[3]), "r"(b[0]), "r"(b[1]));
}
__device__ __forceinline__ void ldsm4(unsigned& r0, unsigned& r1, unsigned& r2, unsigned& r3,
                                      uint32_t a) {
    asm volatile("ldmatrix.sync.aligned.m8n8.x4.shared.b16 {%0,%1,%2,%3}, [%4];"
        : "=r"(r0), "=r"(r1), "=r"(r2), "=r"(r3) : "r"(a));
}
__device__ __forceinline__ void ldsm2(unsigned& r0, unsigned& r1, uint32_t a) {
    asm volatile("ldmatrix.sync.aligned.m8n8.x2.shared.b16 {%0,%1}, [%2];"
        : "=r"(r0), "=r"(r1) : "r"(a));
}
#define MBINIT(a, n) \
    asm volatile("mbarrier.init.shared.b64 [%0], %1;" :: "r"(a), "r"(n) : "memory")
#define MBEXPECT(a, n) \
    asm volatile("mbarrier.arrive.expect_tx.shared.b64 _, [%0], %1;" :: "r"(a), "r"(n) : "memory")
#define MBWAIT(a, ph) \
    asm volatile("{\n\t.reg .pred P;\n\tWL_%=: mbarrier.try_wait.parity.acquire.cta.shared::cta.b64 P, [%0], %1, 0x989680;\n\t@P bra.uni WD_%=;\n\tbra.uni WL_%=;\n\tWD_%=:\n\t}" \
                 :: "r"(a), "r"((uint32_t)(ph)) : "memory")
#define FPROXY() asm volatile("fence.proxy.async.shared::cta;" ::: "memory")

// ---------------- Precompute kernels ----------------

__global__ void k_weff(const float* __restrict__ Wih, const float* __restrict__ Whh,
                       const float* __restrict__ Wfc) {
    __shared__ float wih_s[4][INP];
    int m = blockIdx.x * 256 + threadIdx.x;   // grid.x = 4
    int npb = blockIdx.y * 4;                 // grid.y = 1024
    for (int idx = threadIdx.x; idx < 4 * INP; idx += 256)
        wih_s[idx >> 7][idx & 127] = Wih[permrow(npb + (idx >> 7)) * INP + (idx & 127)];
    __syncthreads();
    float acc[4];
    #pragma unroll
    for (int i = 0; i < 4; i++) acc[i] = Whh[(size_t)permrow(npb + i) * HID + m];
    for (int k = 0; k < INP; k++) {
        float w = Wfc[k * HID + m];
        #pragma unroll
        for (int i = 0; i < 4; i++) acc[i] += wih_s[i][k] * w;
    }
    #pragma unroll
    for (int i = 0; i < 4; i++) {
        int np = npb + i;
        int tile = (np >> 7) * 16 + (m >> 6);
        uint32_t bo = sw128((uint32_t)((np & 127) * 128 + (m & 63) * 2));
        *(__half*)((char*)d_Weff + (size_t)tile * TILEB + bo) = __float2half_rn(acc[i]);
    }
}

__global__ void k_state(const float* __restrict__ hid, const float* __restrict__ cell) {
    int i = blockIdx.x * 256 + threadIdx.x;   // grid 2048
    int b = i >> 10, j = i & 1023;
    int tile = (b >> 7) * 16 + (j >> 6);
    uint32_t bo = sw128((uint32_t)((b & 127) * 128 + (j & 63) * 2));
    *(__half*)((char*)d_hbuf[0] + (size_t)tile * TILEB + bo) = __float2half_rn(hid[i]);
    d_cbuf[i] = cell[i];
}

// u0[b][k] = x0[b][k] - b_fc[k] - h0[b]·W_fc[k]  (block = 8 batch rows, coalesced Wfc)
__global__ void __launch_bounds__(256, 1)
k_u0(const float* __restrict__ xt, const float* __restrict__ hid,
     const float* __restrict__ Wfc, const float* __restrict__ bfc) {
    __shared__ float hs[8][HID];
    const int bq = blockIdx.x;                // 64 blocks
    const int tid = threadIdx.x, lane = tid & 31, w = tid >> 5;
    for (int i = tid; i < 8 * HID; i += 256)
        hs[i >> 10][i & 1023] = hid[(size_t)(bq * 8 + (i >> 10)) * HID + (i & 1023)];
    __syncthreads();
    for (int k = w; k < INP; k += 8) {
        const float* wr = Wfc + (size_t)k * HID;
        float acc[8] = {0, 0, 0, 0, 0, 0, 0, 0};
        for (int i = lane; i < HID; i += 32) {
            float wv = wr[i];
            #pragma unroll
            for (int b8 = 0; b8 < 8; b8++) acc[b8] += hs[b8][i] * wv;
        }
        #pragma unroll
        for (int off = 16; off; off >>= 1)
            #pragma unroll
            for (int b8 = 0; b8 < 8; b8++) acc[b8] += __shfl_xor_sync(0xffffffffu, acc[b8], off);
        if (lane == 0) {
            float bk = bfc[k];
            #pragma unroll
            for (int b8 = 0; b8 < 8; b8++) {
                int b = bq * 8 + b8;
                d_u0[b * INP + k] = xt[b * INP + k] - bk - acc[b8];
            }
        }
    }
}

__global__ void k_beff(const float* __restrict__ Wih, const float* __restrict__ bih,
                       const float* __restrict__ bhh, const float* __restrict__ bfc) {
    int np = blockIdx.x * 256 + threadIdx.x;
    int r = permrow(np);
    float acc = bih[r] + bhh[r];
    for (int k = 0; k < INP; k++) acc += Wih[r * INP + k] * bfc[k];
    d_beff[np] = acc;
}

__global__ void k_d0(const float* __restrict__ Wih) {
    __shared__ float us[4][INP];
    int tid = threadIdx.x;
    int bq = blockIdx.y;
    int np = blockIdx.x * 128 + tid;
    #pragma unroll
    for (int i = 0; i < 4; i++) us[i][tid] = d_u0[(bq * 4 + i) * INP + tid];
    __syncthreads();
    int r = permrow(np);
    float a0 = 0, a1 = 0, a2 = 0, a3 = 0;
    for (int k = 0; k < INP; k++) {
        float w = Wih[r * INP + k];
        a0 += us[0][k] * w; a1 += us[1][k] * w; a2 += us[2][k] * w; a3 += us[3][k] * w;
    }
    d_D0[(size_t)(bq * 4 + 0) * NG + np] = a0;
    d_D0[(size_t)(bq * 4 + 1) * NG + np] = a1;
    d_D0[(size_t)(bq * 4 + 2) * NG + np] = a2;
    d_D0[(size_t)(bq * 4 + 3) * NG + np] = a3;
}

// ---------------- Step kernel ----------------
__global__ void __launch_bounds__(256, 1)
k_step(int t, int par, const float* __restrict__ Wfc) {
    extern __shared__ float sm[];
    __shared__ __align__(8) uint64_t mbf[STG];
    __shared__ float s_beff[128];
    __shared__ float s_w127[32];

    const int tid = threadIdx.x, lane = tid & 31, wid = tid >> 5;
    const int wm = wid & 1, wn = wid >> 1;
    const int gid = lane >> 2, tig = lane & 3;
    const int ntile = blockIdx.x, mtile = blockIdx.y;
    const int m0 = mtile * 128, n0 = ntile * 128;
    const int rlA = lane & 15;
    const int lhA = lane >> 4;
    const int rlB = lane & 7;
    const int lhB = (lane >> 3) & 1;

    if (tid < 32) s_w127[tid] = Wfc[127 * HID + ntile * 32 + tid];
    if (tid < 128) s_beff[tid] = d_beff[n0 + tid];
    if (tid == 0) {
        #pragma unroll
        for (int s = 0; s < STG; s++) MBINIT(s2u(&mbf[s]), 1);
        FPROXY();
    }
    __syncthreads();

    const __half* Asrc = d_hbuf[par] + (size_t)mtile * 16 * TILEHF;
    const __half* Bsrc = d_Weff + (size_t)ntile * 16 * TILEHF;
    const uint32_t smu = s2u(sm);

    if (tid == 0) {
        #pragma unroll
        for (int s = 0; s < STG; s++) {
            MBEXPECT(s2u(&mbf[s]), 2 * TILEB);
            bulkcp(smu + s * 2 * TILEB, Asrc + s * TILEHF, TILEB, s2u(&mbf[s]));
            bulkcp(smu + s * 2 * TILEB + TILEB, Bsrc + s * TILEHF, TILEB, s2u(&mbf[s]));
        }
    }

    float acc[4][4][4];
    #pragma unroll
    for (int a = 0; a < 4; a++)
        #pragma unroll
        for (int b = 0; b < 4; b++)
            #pragma unroll
            for (int c = 0; c < 4; c++) acc[a][b][c] = 0.f;

    for (int c = 0; c < NCH; c++) {
        const int s = c & (STG - 1);
        const int ph = (c >> 2) & 1;
        MBWAIT(s2u(&mbf[s]), ph);

        const uint32_t As = smu + s * 2 * TILEB;
        const uint32_t Bs = As + TILEB;
        #pragma unroll
        for (int k8 = 0; k8 < 32; k8 += 8) {
            const int u0 = k8 >> 2;
            unsigned a[4][4], b[4][2];
            #pragma unroll
            for (int mf = 0; mf < 4; mf++) {
                int row = wm * 64 + mf * 16 + rlA;
                uint32_t addr = As + row * 128 + ((((u0 + lhA) ^ (row & 7)) & 7) << 4);
                ldsm4(a[mf][0], a[mf][1], a[mf][2], a[mf][3], addr);
            }
            #pragma unroll
            for (int nf = 0; nf < 4; nf++) {
                int row = wn * 32 + nf * 8 + rlB;
                uint32_t addr = Bs + row * 128 + ((((u0 + lhB) ^ (row & 7)) & 7) << 4);
                ldsm2(b[nf][0], b[nf][1], addr);
            }
            #pragma unroll
            for (int mf = 0; mf < 4; mf++)
                #pragma unroll
                for (int nf = 0; nf < 4; nf++) mma16(acc[mf][nf], a[mf], b[nf]);
        }
        __syncthreads();
        if (tid == 0 && c + STG < NCH) {
            MBEXPECT(s2u(&mbf[s]), 2 * TILEB);
            bulkcp(smu + s * 2 * TILEB, Asrc + (c + STG) * TILEHF, TILEB, s2u(&mbf[s]));
            bulkcp(smu + s * 2 * TILEB + TILEB, Bsrc + (c + STG) * TILEHF, TILEB, s2u(&mbf[s]));
        }
    }
    __syncthreads();

    #pragma unroll
    for (int mf = 0; mf < 4; mf++)
        #pragma unroll
        for (int nf = 0; nf < 4; nf++) {
            int row = wm * 64 + mf * 16 + gid;
            int col = wn * 32 + nf * 8 + 2 * tig;
            sm[row * 132 + col]           = acc[mf][nf][0];
            sm[row * 132 + col + 1]       = acc[mf][nf][1];
            sm[(row + 8) * 132 + col]     = acc[mf][nf][2];
            sm[(row + 8) * 132 + col + 1] = acc[mf][nf][3];
        }
    __syncthreads();

    {
        const int bl = tid >> 1, jh = tid & 1;
        const int b = m0 + bl;
        float* cb = d_cbuf + (size_t)b * HID + ntile * 32 + jh * 16;
        const float* csm = sm + bl * 132 + jh * 64;
        const float* d0p = d_D0 + (size_t)b * NG + n0 + jh * 64;
        char* hT = (char*)d_hbuf[par ^ 1] + (size_t)(mtile * 16 + (ntile >> 1)) * TILEB;
        const int colbase = (ntile & 1) * 64 + jh * 32;
        float partial = 0.f;

        #pragma unroll
        for (int q = 0; q < 4; q++) {
            float4 cold = *(const float4*)(cb + q * 4);
            float co[4] = {cold.x, cold.y, cold.z, cold.w};
            float hv[4];
            #pragma unroll
            for (int v = 0; v < 4; v++) {
                int g4 = q * 16 + v * 4;
                float gi = csm[g4]     + s_beff[jh * 64 + g4];
                float gf = csm[g4 + 1] + s_beff[jh * 64 + g4 + 1];
                float gg = csm[g4 + 2] + s_beff[jh * 64 + g4 + 2];
                float go = csm[g4 + 3] + s_beff[jh * 64 + g4 + 3];
                if (t == 0) {
                    float4 dd = *(const float4*)(d0p + g4);
                    gi += dd.x; gf += dd.y; gg += dd.z; go += dd.w;
                }
                float cn = sigm(gf) * co[v] + sigm(gi) * tanhf(gg);
                hv[v] = sigm(go) * tanhf(cn);
                co[v] = cn;
                partial += hv[v] * s_w127[jh * 16 + q * 4 + v];
            }
            *(float4*)(cb + q * 4) = make_float4(co[0], co[1], co[2], co[3]);
            uint32_t bo = (uint32_t)(bl * 128 + colbase + q * 8);
            __half2 p01 = __floats2half2_rn(hv[0], hv[1]);
            __half2 p23 = __floats2half2_rn(hv[2], hv[3]);
            uint32_t sw = sw128(bo);
            *(__half2*)(hT + sw)     = p01;
            *(__half2*)(hT + sw + 4) = p23;
        }
        partial += __shfl_xor_sync(0xffffffffu, partial, 1);
        if (jh == 0) d_part[(size_t)t * (32 * BSZ) + ntile * BSZ + b] = partial;
    }
}

__global__ void k_reduce(float* __restrict__ out, const float* __restrict__ bfc) {
    int idx = blockIdx.x * 256 + threadIdx.x;
    if (idx >= BSZ * SEQ) return;
    int b = idx / SEQ, t = idx % SEQ;
    float s = bfc[127];
    #pragma unroll 8
    for (int nt = 0; nt < 32; nt++) s += d_part[(size_t)t * (32 * BSZ) + nt * BSZ + b];
    out[idx] = s;
}

extern "C" void kernel_launch(void* const* d_in, const int* in_sizes, int n_in,
                              void* d_out, int out_size) {
    const float* xt   = (const float*)d_in[0];
    const float* hid  = (const float*)d_in[1];
    const float* cell = (const float*)d_in[2];
    const float* Wih  = (const float*)d_in[3];
    const float* Whh  = (const float*)d_in[4];
    const float* bih  = (const float*)d_in[5];
    const float* bhh  = (const float*)d_in[6];
    const float* Wfc  = (const float*)d_in[7];
    const float* bfc  = (const float*)d_in[8];
    float* out = (float*)d_out;

    cudaFuncSetAttribute(k_step, cudaFuncAttributeMaxDynamicSharedMemorySize, SMEM_BYTES);

    k_weff<<<dim3(4, 1024), 256>>>(Wih, Whh, Wfc);
    k_state<<<2048, 256>>>(hid, cell);
    k_u0<<<64, 256>>>(xt, hid, Wfc, bfc);
    k_beff<<<16, 256>>>(Wih, bih, bhh, bfc);
    k_d0<<<dim3(32, 128), 128>>>(Wih);
    for (int t = 0; t < SEQ; t++)
        k_step<<<dim3(32, 4), 256, SMEM_BYTES>>>(t, t & 1, Wfc);
    k_reduce<<<192, 256>>>(out, bfc);
}

// round 13
// speedup vs baseline: 1.5704x; 1.0366x over previous
#include <cuda_runtime.h>
#include <cuda_fp16.h>
#include <cstdint>

// Sizes
#define BSZ 512
#define HID 1024
#define NG  4096
#define INP 128
#define SEQ 96
#define NCH 16             // K chunks of 64 halfs
#define TILEHF 8192        // halfs per 128x64 tile
#define TILEB 16384        // bytes per tile (128 rows x 128 B)
#define STG 4              // pipeline stages
#define SMEM_BYTES (STG * 2 * TILEB)   // 131072 dynamic

// Scratch (__device__ globals; no cudaMalloc allowed)
__device__ __align__(128) __half d_Weff[(size_t)NG * HID];    // tiled+swizzled [ntile*16+ch][128][64]
__device__ float d_beff[NG];                                  // permuted linear
__device__ float d_D0[(size_t)BSZ * NG];                      // step-0 correction [b][n']
__device__ float d_u0[BSZ * INP];
__device__ __align__(128) __half d_hbuf[2][(size_t)BSZ * HID]; // tiled+swizzled [mtile*16+ch][128][64]
__device__ float d_cbuf[(size_t)BSZ * HID];                   // linear [b][j]
__device__ float d_part[(size_t)SEQ * 32 * BSZ];

__device__ __forceinline__ float sigm(float x) { return 1.0f / (1.0f + __expf(-x)); }
__device__ __forceinline__ int permrow(int np) { return ((np & 3) << 10) | (np >> 2); }
__device__ __forceinline__ uint32_t sw128(uint32_t o) { return o ^ ((o >> 3) & 0x70); }

__device__ __forceinline__ uint32_t s2u(const void* p) {
    uint32_t a;
    asm("{ .reg .u64 t; cvta.to.shared.u64 t, %1; cvt.u32.u64 %0, t; }" : "=r"(a) : "l"(p));
    return a;
}
__device__ __forceinline__ void bulkcp(uint32_t dst, const void* src, uint32_t bytes, uint32_t mbar) {
    asm volatile(
        "cp.async.bulk.shared::cluster.global.mbarrier::complete_tx::bytes [%0], [%1], %2, [%3];"
        :: "r"(dst), "l"(src), "r"(bytes), "r"(mbar) : "memory");
}
__device__ __forceinline__ void mma16(float* c, const unsigned* a, const unsigned* b) {
    asm volatile(
        "mma.sync.aligned.m16n8k16.row.col.f32.f16.f16.f32 "
        "{%0,%1,%2,%3}, {%4,%5,%6,%7}, {%8,%9}, {%0,%1,%2,%3};"
        : "+f"(c[0]), "+f"(c[1]), "+f"(c[2]), "+f"(c[3])
        : "r"(a[0]), "r"(a[1]), "r"(a[2]), "r"(a[3]), "r"(b[0]), "r"(b[1]));
}
__device__ __forceinline__ void ldsm4(unsigned& r0, unsigned& r1, unsigned& r2, unsigned& r3,
                                      uint32_t a) {
    asm volatile("ldmatrix.sync.aligned.m8n8.x4.shared.b16 {%0,%1,%2,%3}, [%4];"
        : "=r"(r0), "=r"(r1), "=r"(r2), "=r"(r3) : "r"(a));
}
__device__ __forceinline__ void ldsm2(unsigned& r0, unsigned& r1, uint32_t a) {
    asm volatile("ldmatrix.sync.aligned.m8n8.x2.shared.b16 {%0,%1}, [%2];"
        : "=r"(r0), "=r"(r1) : "r"(a));
}
#define MBINIT(a, n) \
    asm volatile("mbarrier.init.shared.b64 [%0], %1;" :: "r"(a), "r"(n) : "memory")
#define MBEXPECT(a, n) \
    asm volatile("mbarrier.arrive.expect_tx.shared.b64 _, [%0], %1;" :: "r"(a), "r"(n) : "memory")
#define MBWAIT(a, ph) \
    asm volatile("{\n\t.reg .pred P;\n\tWL_%=: mbarrier.try_wait.parity.acquire.cta.shared::cta.b64 P, [%0], %1, 0x989680;\n\t@P bra.uni WD_%=;\n\tbra.uni WL_%=;\n\tWD_%=:\n\t}" \
                 :: "r"(a), "r"((uint32_t)(ph)) : "memory")
#define FPROXY() asm volatile("fence.proxy.async.shared::cta;" ::: "memory")

// ---------------- Precompute kernels ----------------

// W_eff[n'][m] = W_hh[r][m] + sum_k W_ih[r][k]*W_fc[k][m]; 16 gate rows per block
__global__ void __launch_bounds__(256, 1)
k_weff(const float* __restrict__ Wih, const float* __restrict__ Whh,
       const float* __restrict__ Wfc) {
    __shared__ float wih_s[16][INP];
    int m = blockIdx.x * 256 + threadIdx.x;   // grid.x = 4
    int npb = blockIdx.y * 16;                // grid.y = 256
    for (int idx = threadIdx.x; idx < 16 * INP; idx += 256)
        wih_s[idx >> 7][idx & 127] = Wih[permrow(npb + (idx >> 7)) * INP + (idx & 127)];
    __syncthreads();
    float acc[16];
    #pragma unroll
    for (int i = 0; i < 16; i++) acc[i] = Whh[(size_t)permrow(npb + i) * HID + m];
    for (int k = 0; k < INP; k++) {
        float w = Wfc[k * HID + m];
        #pragma unroll
        for (int i = 0; i < 16; i++) acc[i] += wih_s[i][k] * w;
    }
    #pragma unroll
    for (int i = 0; i < 16; i++) {
        int np = npb + i;
        int tile = (np >> 7) * 16 + (m >> 6);
        uint32_t bo = sw128((uint32_t)((np & 127) * 128 + (m & 63) * 2));
        *(__half*)((char*)d_Weff + (size_t)tile * TILEB + bo) = __float2half_rn(acc[i]);
    }
}

__global__ void k_state(const float* __restrict__ hid, const float* __restrict__ cell) {
    int i = blockIdx.x * 256 + threadIdx.x;   // grid 2048
    int b = i >> 10, j = i & 1023;
    int tile = (b >> 7) * 16 + (j >> 6);
    uint32_t bo = sw128((uint32_t)((b & 127) * 128 + (j & 63) * 2));
    *(__half*)((char*)d_hbuf[0] + (size_t)tile * TILEB + bo) = __float2half_rn(hid[i]);
    d_cbuf[i] = cell[i];
}

// u0[b][k] = x0[b][k] - b_fc[k] - h0[b]·W_fc[k]  (block = 8 batch rows, coalesced Wfc)
__global__ void __launch_bounds__(256, 1)
k_u0(const float* __restrict__ xt, const float* __restrict__ hid,
     const float* __restrict__ Wfc, const float* __restrict__ bfc) {
    __shared__ float hs[8][HID];
    const int bq = blockIdx.x;                // 64 blocks
    const int tid = threadIdx.x, lane = tid & 31, w = tid >> 5;
    for (int i = tid; i < 8 * HID; i += 256)
        hs[i >> 10][i & 1023] = hid[(size_t)(bq * 8 + (i >> 10)) * HID + (i & 1023)];
    __syncthreads();
    for (int k = w; k < INP; k += 8) {
        const float* wr = Wfc + (size_t)k * HID;
        float acc[8] = {0, 0, 0, 0, 0, 0, 0, 0};
        for (int i = lane; i < HID; i += 32) {
            float wv = wr[i];
            #pragma unroll
            for (int b8 = 0; b8 < 8; b8++) acc[b8] += hs[b8][i] * wv;
        }
        #pragma unroll
        for (int off = 16; off; off >>= 1)
            #pragma unroll
            for (int b8 = 0; b8 < 8; b8++) acc[b8] += __shfl_xor_sync(0xffffffffu, acc[b8], off);
        if (lane == 0) {
            float bk = bfc[k];
            #pragma unroll
            for (int b8 = 0; b8 < 8; b8++) {
                int b = bq * 8 + b8;
                d_u0[b * INP + k] = xt[b * INP + k] - bk - acc[b8];
            }
        }
    }
}

__global__ void k_beff(const float* __restrict__ Wih, const float* __restrict__ bih,
                       const float* __restrict__ bhh, const float* __restrict__ bfc) {
    int np = blockIdx.x * 256 + threadIdx.x;
    int r = permrow(np);
    float acc = bih[r] + bhh[r];
    for (int k = 0; k < INP; k++) acc += Wih[r * INP + k] * bfc[k];
    d_beff[np] = acc;
}

__global__ void k_d0(const float* __restrict__ Wih) {
    __shared__ float us[4][INP];
    int tid = threadIdx.x;
    int bq = blockIdx.y;
    int np = blockIdx.x * 128 + tid;
    #pragma unroll
    for (int i = 0; i < 4; i++) us[i][tid] = d_u0[(bq * 4 + i) * INP + tid];
    __syncthreads();
    int r = permrow(np);
    float a0 = 0, a1 = 0, a2 = 0, a3 = 0;
    for (int k = 0; k < INP; k++) {
        float w = Wih[r * INP + k];
        a0 += us[0][k] * w; a1 += us[1][k] * w; a2 += us[2][k] * w; a3 += us[3][k] * w;
    }
    d_D0[(size_t)(bq * 4 + 0) * NG + np] = a0;
    d_D0[(size_t)(bq * 4 + 1) * NG + np] = a1;
    d_D0[(size_t)(bq * 4 + 2) * NG + np] = a2;
    d_D0[(size_t)(bq * 4 + 3) * NG + np] = a3;
}

// ---------------- Step kernel (PDL: B copies pre-sync, A copies post-sync) ----------------
__global__ void __launch_bounds__(256, 1)
k_step(int t, int par, const float* __restrict__ Wfc) {
    extern __shared__ float sm[];
    __shared__ __align__(8) uint64_t mbf[STG];
    __shared__ float s_beff[128];
    __shared__ float s_w127[32];

    const int tid = threadIdx.x, lane = tid & 31, wid = tid >> 5;
    const int wm = wid & 1, wn = wid >> 1;
    const int gid = lane >> 2, tig = lane & 3;
    const int ntile = blockIdx.x, mtile = blockIdx.y;
    const int m0 = mtile * 128, n0 = ntile * 128;
    const int rlA = lane & 15;
    const int lhA = lane >> 4;
    const int rlB = lane & 7;
    const int lhB = (lane >> 3) & 1;

    // Preamble: only static data (d_beff, Wfc, d_Weff) touched before the dependency sync.
    if (tid < 32) s_w127[tid] = Wfc[127 * HID + ntile * 32 + tid];
    if (tid < 128) s_beff[tid] = d_beff[n0 + tid];
    if (tid == 0) {
        #pragma unroll
        for (int s = 0; s < STG; s++) MBINIT(s2u(&mbf[s]), 2);   // 2 arrivals: B-issue + A-issue
        FPROXY();
    }
    __syncthreads();

    const __half* Asrc = d_hbuf[par] + (size_t)mtile * 16 * TILEHF;
    const __half* Bsrc = d_Weff + (size_t)ntile * 16 * TILEHF;
    const uint32_t smu = s2u(sm);

    // Phase 1: B (static weights) — may run while the previous step is still executing.
    if (tid == 0) {
        #pragma unroll
        for (int s = 0; s < STG; s++) {
            MBEXPECT(s2u(&mbf[s]), TILEB);
            bulkcp(smu + s * 2 * TILEB + TILEB, Bsrc + s * TILEHF, TILEB, s2u(&mbf[s]));
        }
    }

    // Let the next step launch early; then wait for the previous step's grid.
    cudaTriggerProgrammaticLaunchCompletion();
    cudaGridDependencySynchronize();

    // Phase 2: A (h from previous step) — only after upstream completion.
    if (tid == 0) {
        #pragma unroll
        for (int s = 0; s < STG; s++) {
            MBEXPECT(s2u(&mbf[s]), TILEB);
            bulkcp(smu + s * 2 * TILEB, Asrc + s * TILEHF, TILEB, s2u(&mbf[s]));
        }
    }

    float acc[4][4][4];
    #pragma unroll
    for (int a = 0; a < 4; a++)
        #pragma unroll
        for (int b = 0; b < 4; b++)
            #pragma unroll
            for (int c = 0; c < 4; c++) acc[a][b][c] = 0.f;

    for (int c = 0; c < NCH; c++) {
        const int s = c & (STG - 1);
        const int ph = (c >> 2) & 1;
        MBWAIT(s2u(&mbf[s]), ph);

        const uint32_t As = smu + s * 2 * TILEB;
        const uint32_t Bs = As + TILEB;
        #pragma unroll
        for (int k8 = 0; k8 < 32; k8 += 8) {
            const int u0 = k8 >> 2;
            unsigned a[4][4], b[4][2];
            #pragma unroll
            for (int mf = 0; mf < 4; mf++) {
                int row = wm * 64 + mf * 16 + rlA;
                uint32_t addr = As + row * 128 + ((((u0 + lhA) ^ (row & 7)) & 7) << 4);
                ldsm4(a[mf][0], a[mf][1], a[mf][2], a[mf][3], addr);
            }
            #pragma unroll
            for (int nf = 0; nf < 4; nf++) {
                int row = wn * 32 + nf * 8 + rlB;
                uint32_t addr = Bs + row * 128 + ((((u0 + lhB) ^ (row & 7)) & 7) << 4);
                ldsm2(b[nf][0], b[nf][1], addr);
            }
            #pragma unroll
            for (int mf = 0; mf < 4; mf++)
                #pragma unroll
                for (int nf = 0; nf < 4; nf++) mma16(acc[mf][nf], a[mf], b[nf]);
        }
        __syncthreads();
        if (tid == 0 && c + STG < NCH) {
            MBEXPECT(s2u(&mbf[s]), TILEB);
            bulkcp(smu + s * 2 * TILEB, Asrc + (c + STG) * TILEHF, TILEB, s2u(&mbf[s]));
            MBEXPECT(s2u(&mbf[s]), TILEB);
            bulkcp(smu + s * 2 * TILEB + TILEB, Bsrc + (c + STG) * TILEHF, TILEB, s2u(&mbf[s]));
        }
    }
    __syncthreads();

    #pragma unroll
    for (int mf = 0; mf < 4; mf++)
        #pragma unroll
        for (int nf = 0; nf < 4; nf++) {
            int row = wm * 64 + mf * 16 + gid;
            int col = wn * 32 + nf * 8 + 2 * tig;
            sm[row * 132 + col]           = acc[mf][nf][0];
            sm[row * 132 + col + 1]       = acc[mf][nf][1];
            sm[(row + 8) * 132 + col]     = acc[mf][nf][2];
            sm[(row + 8) * 132 + col + 1] = acc[mf][nf][3];
        }
    __syncthreads();

    {
        const int bl = tid >> 1, jh = tid & 1;
        const int b = m0 + bl;
        float* cb = d_cbuf + (size_t)b * HID + ntile * 32 + jh * 16;
        const float* csm = sm + bl * 132 + jh * 64;
        const float* d0p = d_D0 + (size_t)b * NG + n0 + jh * 64;
        char* hT = (char*)d_hbuf[par ^ 1] + (size_t)(mtile * 16 + (ntile >> 1)) * TILEB;
        const int colbase = (ntile & 1) * 64 + jh * 32;
        float partial = 0.f;

        #pragma unroll
        for (int q = 0; q < 4; q++) {
            float4 cold = *(const float4*)(cb + q * 4);
            float co[4] = {cold.x, cold.y, cold.z, cold.w};
            float hv[4];
            #pragma unroll
            for (int v = 0; v < 4; v++) {
                int g4 = q * 16 + v * 4;
                float gi = csm[g4]     + s_beff[jh * 64 + g4];
                float gf = csm[g4 + 1] + s_beff[jh * 64 + g4 + 1];
                float gg = csm[g4 + 2] + s_beff[jh * 64 + g4 + 2];
                float go = csm[g4 + 3] + s_beff[jh * 64 + g4 + 3];
                if (t == 0) {
                    float4 dd = *(const float4*)(d0p + g4);
                    gi += dd.x; gf += dd.y; gg += dd.z; go += dd.w;
                }
                float cn = sigm(gf) * co[v] + sigm(gi) * tanhf(gg);
                hv[v] = sigm(go) * tanhf(cn);
                co[v] = cn;
                partial += hv[v] * s_w127[jh * 16 + q * 4 + v];
            }
            *(float4*)(cb + q * 4) = make_float4(co[0], co[1], co[2], co[3]);
            uint32_t bo = (uint32_t)(bl * 128 + colbase + q * 8);
            __half2 p01 = __floats2half2_rn(hv[0], hv[1]);
            __half2 p23 = __floats2half2_rn(hv[2], hv[3]);
            uint32_t sw = sw128(bo);
            *(__half2*)(hT + sw)     = p01;
            *(__half2*)(hT + sw + 4) = p23;
        }
        partial += __shfl_xor_sync(0xffffffffu, partial, 1);
        if (jh == 0) d_part[(size_t)t * (32 * BSZ) + ntile * BSZ + b] = partial;
    }
}

__global__ void k_reduce(float* __restrict__ out, const float* __restrict__ bfc) {
    int idx = blockIdx.x * 256 + threadIdx.x;
    if (idx >= BSZ * SEQ) return;
    int b = idx / SEQ, t = idx % SEQ;
    float s = bfc[127];
    #pragma unroll 8
    for (int nt = 0; nt < 32; nt++) s += d_part[(size_t)t * (32 * BSZ) + nt * BSZ + b];
    out[idx] = s;
}

extern "C" void kernel_launch(void* const* d_in, const int* in_sizes, int n_in,
                              void* d_out, int out_size) {
    const float* xt   = (const float*)d_in[0];
    const float* hid  = (const float*)d_in[1];
    const float* cell = (const float*)d_in[2];
    const float* Wih  = (const float*)d_in[3];
    const float* Whh  = (const float*)d_in[4];
    const float* bih  = (const float*)d_in[5];
    const float* bhh  = (const float*)d_in[6];
    const float* Wfc  = (const float*)d_in[7];
    const float* bfc  = (const float*)d_in[8];
    float* out = (float*)d_out;

    cudaFuncSetAttribute(k_step, cudaFuncAttributeMaxDynamicSharedMemorySize, SMEM_BYTES);

    k_weff<<<dim3(4, 256), 256>>>(Wih, Whh, Wfc);
    k_state<<<2048, 256>>>(hid, cell);
    k_u0<<<64, 256>>>(xt, hid, Wfc, bfc);
    k_beff<<<16, 256>>>(Wih, bih, bhh, bfc);
    k_d0<<<dim3(32, 128), 128>>>(Wih);

    // 96 dependent steps with Programmatic Dependent Launch: each step may
    // launch while its predecessor is finishing (preamble + B copies overlap);
    // cudaGridDependencySynchronize() in-kernel enforces the real dependency.
    cudaLaunchAttribute at[1];
    at[0].id = cudaLaunchAttributeProgrammaticStreamSerialization;
    at[0].val.programmaticStreamSerializationAllowed = 1;
    cudaLaunchConfig_t cfg = {};
    cfg.gridDim = dim3(32, 4);
    cfg.blockDim = dim3(256);
    cfg.dynamicSmemBytes = SMEM_BYTES;
    cfg.stream = 0;
    cfg.attrs = at;
    cfg.numAttrs = 1;
    for (int t = 0; t < SEQ; t++)
        cudaLaunchKernelEx(&cfg, k_step, t, t & 1, Wfc);

    k_reduce<<<192, 256>>>(out, bfc);
}

// round 14
// speedup vs baseline: 1.6862x; 1.0737x over previous
#include <cuda_runtime.h>
#include <cuda_fp16.h>
#include <cstdint>

// Sizes
#define BSZ 512
#define HID 1024
#define NG  4096
#define INP 128
#define SEQ 96
#define NCH 16             // K chunks of 64 halfs
#define ATILEHF 8192       // halfs per A chunk tile (128 x 64)
#define ATILEB 16384       // bytes per A chunk tile
#define BTILEHF 4096       // halfs per B chunk tile (64 x 64)
#define BTILEB 8192        // bytes per B chunk tile
#define STAGEB (ATILEB + BTILEB)       // 24576
#define STG 4              // pipeline stages
#define SMEM_BYTES (STG * STAGEB)      // 98304 -> 2 CTAs/SM (192KB of 228KB)

// Scratch (__device__ globals; no cudaMalloc allowed)
__device__ __align__(128) __half d_Weff[(size_t)NG * HID];    // [ntile*16+ch][64][64] swizzled
__device__ float d_beff[NG];                                  // permuted linear
__device__ float d_D0[(size_t)BSZ * NG];                      // step-0 correction [b][n']
__device__ float d_u0[BSZ * INP];
__device__ __align__(128) __half d_hbuf[2][(size_t)BSZ * HID]; // [mtile*16+ch][128][64] swizzled
__device__ float d_cbuf[(size_t)BSZ * HID];                   // linear [b][j]
__device__ float d_part[(size_t)SEQ * 64 * BSZ];              // [t][ntile][b]

__device__ __forceinline__ float sigm(float x) { return 1.0f / (1.0f + __expf(-x)); }
__device__ __forceinline__ int permrow(int np) { return ((np & 3) << 10) | (np >> 2); }
__device__ __forceinline__ uint32_t sw128(uint32_t o) { return o ^ ((o >> 3) & 0x70); }

__device__ __forceinline__ uint32_t s2u(const void* p) {
    uint32_t a;
    asm("{ .reg .u64 t; cvta.to.shared.u64 t, %1; cvt.u32.u64 %0, t; }" : "=r"(a) : "l"(p));
    return a;
}
__device__ __forceinline__ void bulkcp(uint32_t dst, const void* src, uint32_t bytes, uint32_t mbar) {
    asm volatile(
        "cp.async.bulk.shared::cluster.global.mbarrier::complete_tx::bytes [%0], [%1], %2, [%3];"
        :: "r"(dst), "l"(src), "r"(bytes), "r"(mbar) : "memory");
}
__device__ __forceinline__ void mma16(float* c, const unsigned* a, const unsigned* b) {
    asm volatile(
        "mma.sync.aligned.m16n8k16.row.col.f32.f16.f16.f32 "
        "{%0,%1,%2,%3}, {%4,%5,%6,%7}, {%8,%9}, {%0,%1,%2,%3};"
        : "+f"(c[0]), "+f"(c[1]), "+f"(c[2]), "+f"(c[3])
        : "r"(a[0]), "r"(a[1]), "r"(a[2]), "r"(a[3]), "r"(b[0]), "r"(b[1]));
}
__device__ __forceinline__ void ldsm4(unsigned& r0, unsigned& r1, unsigned& r2, unsigned& r3,
                                      uint32_t a) {
    asm volatile("ldmatrix.sync.aligned.m8n8.x4.shared.b16 {%0,%1,%2,%3}, [%4];"
        : "=r"(r0), "=r"(r1), "=r"(r2), "=r"(r3) : "r"(a));
}
__device__ __forceinline__ void ldsm2(unsigned& r0, unsigned& r1, uint32_t a) {
    asm volatile("ldmatrix.sync.aligned.m8n8.x2.shared.b16 {%0,%1}, [%2];"
        : "=r"(r0), "=r"(r1) : "r"(a));
}
#define MBINIT(a, n) \
    asm volatile("mbarrier.init.shared.b64 [%0], %1;" :: "r"(a), "r"(n) : "memory")
#define MBEXPECT(a, n) \
    asm volatile("mbarrier.arrive.expect_tx.shared.b64 _, [%0], %1;" :: "r"(a), "r"(n) : "memory")
#define MBWAIT(a, ph) \
    asm volatile("{\n\t.reg .pred P;\n\tWL_%=: mbarrier.try_wait.parity.acquire.cta.shared::cta.b64 P, [%0], %1, 0x989680;\n\t@P bra.uni WD_%=;\n\tbra.uni WL_%=;\n\tWD_%=:\n\t}" \
                 :: "r"(a), "r"((uint32_t)(ph)) : "memory")
#define FPROXY() asm volatile("fence.proxy.async.shared::cta;" ::: "memory")

// ---------------- Precompute kernels ----------------

// W_eff[n'][m] = W_hh[r][m] + sum_k W_ih[r][k]*W_fc[k][m]; B tiles now 64 rows
__global__ void __launch_bounds__(256, 1)
k_weff(const float* __restrict__ Wih, const float* __restrict__ Whh,
       const float* __restrict__ Wfc) {
    __shared__ float wih_s[16][INP];
    int m = blockIdx.x * 256 + threadIdx.x;   // grid.x = 4
    int npb = blockIdx.y * 16;                // grid.y = 256
    for (int idx = threadIdx.x; idx < 16 * INP; idx += 256)
        wih_s[idx >> 7][idx & 127] = Wih[permrow(npb + (idx >> 7)) * INP + (idx & 127)];
    __syncthreads();
    float acc[16];
    #pragma unroll
    for (int i = 0; i < 16; i++) acc[i] = Whh[(size_t)permrow(npb + i) * HID + m];
    for (int k = 0; k < INP; k++) {
        float w = Wfc[k * HID + m];
        #pragma unroll
        for (int i = 0; i < 16; i++) acc[i] += wih_s[i][k] * w;
    }
    #pragma unroll
    for (int i = 0; i < 16; i++) {
        int np = npb + i;
        int tile = (np >> 6) * 16 + (m >> 6);     // 64-row B tiles
        uint32_t bo = sw128((uint32_t)((np & 63) * 128 + (m & 63) * 2));
        *(__half*)((char*)d_Weff + (size_t)tile * BTILEB + bo) = __float2half_rn(acc[i]);
    }
}

__global__ void k_state(const float* __restrict__ hid, const float* __restrict__ cell) {
    int i = blockIdx.x * 256 + threadIdx.x;   // grid 2048
    int b = i >> 10, j = i & 1023;
    int tile = (b >> 7) * 16 + (j >> 6);
    uint32_t bo = sw128((uint32_t)((b & 127) * 128 + (j & 63) * 2));
    *(__half*)((char*)d_hbuf[0] + (size_t)tile * ATILEB + bo) = __float2half_rn(hid[i]);
    d_cbuf[i] = cell[i];
}

// u0[b][k] = x0[b][k] - b_fc[k] - h0[b]·W_fc[k]
__global__ void __launch_bounds__(256, 1)
k_u0(const float* __restrict__ xt, const float* __restrict__ hid,
     const float* __restrict__ Wfc, const float* __restrict__ bfc) {
    __shared__ float hs[8][HID];
    const int bq = blockIdx.x;                // 64 blocks
    const int tid = threadIdx.x, lane = tid & 31, w = tid >> 5;
    for (int i = tid; i < 8 * HID; i += 256)
        hs[i >> 10][i & 1023] = hid[(size_t)(bq * 8 + (i >> 10)) * HID + (i & 1023)];
    __syncthreads();
    for (int k = w; k < INP; k += 8) {
        const float* wr = Wfc + (size_t)k * HID;
        float acc[8] = {0, 0, 0, 0, 0, 0, 0, 0};
        for (int i = lane; i < HID; i += 32) {
            float wv = wr[i];
            #pragma unroll
            for (int b8 = 0; b8 < 8; b8++) acc[b8] += hs[b8][i] * wv;
        }
        #pragma unroll
        for (int off = 16; off; off >>= 1)
            #pragma unroll
            for (int b8 = 0; b8 < 8; b8++) acc[b8] += __shfl_xor_sync(0xffffffffu, acc[b8], off);
        if (lane == 0) {
            float bk = bfc[k];
            #pragma unroll
            for (int b8 = 0; b8 < 8; b8++) {
                int b = bq * 8 + b8;
                d_u0[b * INP + k] = xt[b * INP + k] - bk - acc[b8];
            }
        }
    }
}

__global__ void k_beff(const float* __restrict__ Wih, const float* __restrict__ bih,
                       const float* __restrict__ bhh, const float* __restrict__ bfc) {
    int np = blockIdx.x * 256 + threadIdx.x;
    int r = permrow(np);
    float acc = bih[r] + bhh[r];
    for (int k = 0; k < INP; k++) acc += Wih[r * INP + k] * bfc[k];
    d_beff[np] = acc;
}

__global__ void k_d0(const float* __restrict__ Wih) {
    __shared__ float us[4][INP];
    int tid = threadIdx.x;
    int bq = blockIdx.y;
    int np = blockIdx.x * 128 + tid;
    #pragma unroll
    for (int i = 0; i < 4; i++) us[i][tid] = d_u0[(bq * 4 + i) * INP + tid];
    __syncthreads();
    int r = permrow(np);
    float a0 = 0, a1 = 0, a2 = 0, a3 = 0;
    for (int k = 0; k < INP; k++) {
        float w = Wih[r * INP + k];
        a0 += us[0][k] * w; a1 += us[1][k] * w; a2 += us[2][k] * w; a3 += us[3][k] * w;
    }
    d_D0[(size_t)(bq * 4 + 0) * NG + np] = a0;
    d_D0[(size_t)(bq * 4 + 1) * NG + np] = a1;
    d_D0[(size_t)(bq * 4 + 2) * NG + np] = a2;
    d_D0[(size_t)(bq * 4 + 3) * NG + np] = a3;
}

// ---------------- Step kernel: tile 128M x 64N, 2 CTAs/SM, PDL ----------------
__global__ void __launch_bounds__(256, 2)
k_step(int t, int par, const float* __restrict__ Wfc) {
    extern __shared__ float sm[];
    __shared__ __align__(8) uint64_t mbf[STG];
    __shared__ float s_beff[64];
    __shared__ float s_w127[16];

    const int tid = threadIdx.x, lane = tid & 31, wid = tid >> 5;
    const int wm = wid & 3, wn = wid >> 2;        // 4 M-warps x 2 N-warps (32M x 32N each)
    const int gid = lane >> 2, tig = lane & 3;
    const int ntile = blockIdx.x, mtile = blockIdx.y;   // 64 x 4
    const int m0 = mtile * 128, n0 = ntile * 64;
    const int rlA = lane & 15;
    const int lhA = lane >> 4;
    const int rlB = lane & 7;
    const int lhB = (lane >> 3) & 1;

    // Preamble: only static data touched before the dependency sync.
    if (tid < 16) s_w127[tid] = Wfc[127 * HID + ntile * 16 + tid];
    if (tid < 64) s_beff[tid] = d_beff[n0 + tid];
    if (tid == 0) {
        #pragma unroll
        for (int s = 0; s < STG; s++) MBINIT(s2u(&mbf[s]), 2);
        FPROXY();
    }
    __syncthreads();

    const __half* Asrc = d_hbuf[par] + (size_t)mtile * 16 * ATILEHF;
    const __half* Bsrc = d_Weff + (size_t)ntile * 16 * BTILEHF;
    const uint32_t smu = s2u(sm);

    // Phase 1: B (static weights) — overlaps the previous step via PDL.
    if (tid == 0) {
        #pragma unroll
        for (int s = 0; s < STG; s++) {
            MBEXPECT(s2u(&mbf[s]), BTILEB);
            bulkcp(smu + s * STAGEB + ATILEB, Bsrc + s * BTILEHF, BTILEB, s2u(&mbf[s]));
        }
    }

    cudaTriggerProgrammaticLaunchCompletion();
    cudaGridDependencySynchronize();

    // Phase 2: A (h from previous step).
    if (tid == 0) {
        #pragma unroll
        for (int s = 0; s < STG; s++) {
            MBEXPECT(s2u(&mbf[s]), ATILEB);
            bulkcp(smu + s * STAGEB, Asrc + s * ATILEHF, ATILEB, s2u(&mbf[s]));
        }
    }

    float acc[2][4][4];
    #pragma unroll
    for (int a = 0; a < 2; a++)
        #pragma unroll
        for (int b = 0; b < 4; b++)
            #pragma unroll
            for (int c = 0; c < 4; c++) acc[a][b][c] = 0.f;

    for (int c = 0; c < NCH; c++) {
        const int s = c & (STG - 1);
        const int ph = (c >> 2) & 1;
        MBWAIT(s2u(&mbf[s]), ph);

        const uint32_t As = smu + s * STAGEB;
        const uint32_t Bs = As + ATILEB;
        #pragma unroll
        for (int k8 = 0; k8 < 32; k8 += 8) {
            const int u0 = k8 >> 2;
            unsigned a[2][4], b[4][2];
            #pragma unroll
            for (int mf = 0; mf < 2; mf++) {
                int row = wm * 32 + mf * 16 + rlA;
                uint32_t addr = As + row * 128 + ((((u0 + lhA) ^ (row & 7)) & 7) << 4);
                ldsm4(a[mf][0], a[mf][1], a[mf][2], a[mf][3], addr);
            }
            #pragma unroll
            for (int nf = 0; nf < 4; nf++) {
                int row = wn * 32 + nf * 8 + rlB;
                uint32_t addr = Bs + row * 128 + ((((u0 + lhB) ^ (row & 7)) & 7) << 4);
                ldsm2(b[nf][0], b[nf][1], addr);
            }
            #pragma unroll
            for (int mf = 0; mf < 2; mf++)
                #pragma unroll
                for (int nf = 0; nf < 4; nf++) mma16(acc[mf][nf], a[mf], b[nf]);
        }
        __syncthreads();
        if (tid == 0 && c + STG < NCH) {
            MBEXPECT(s2u(&mbf[s]), ATILEB);
            bulkcp(smu + s * STAGEB, Asrc + (c + STG) * ATILEHF, ATILEB, s2u(&mbf[s]));
            MBEXPECT(s2u(&mbf[s]), BTILEB);
            bulkcp(smu + s * STAGEB + ATILEB, Bsrc + (c + STG) * BTILEHF, BTILEB, s2u(&mbf[s]));
        }
    }
    __syncthreads();

    // dump C tile (128 x 64, stride 68)
    #pragma unroll
    for (int mf = 0; mf < 2; mf++)
        #pragma unroll
        for (int nf = 0; nf < 4; nf++) {
            int row = wm * 32 + mf * 16 + gid;
            int col = wn * 32 + nf * 8 + 2 * tig;
            sm[row * 68 + col]           = acc[mf][nf][0];
            sm[row * 68 + col + 1]       = acc[mf][nf][1];
            sm[(row + 8) * 68 + col]     = acc[mf][nf][2];
            sm[(row + 8) * 68 + col + 1] = acc[mf][nf][3];
        }
    __syncthreads();

    // Fused LSTM epilogue: thread = (batch row bl, half jh of the 16 hidden units)
    {
        const int bl = tid >> 1, jh = tid & 1;
        const int b = m0 + bl;
        float* cb = d_cbuf + (size_t)b * HID + ntile * 16 + jh * 8;
        const float* csm = sm + bl * 68 + jh * 32;
        const float* d0p = d_D0 + (size_t)b * NG + n0 + jh * 32;
        char* hT = (char*)d_hbuf[par ^ 1] + (size_t)(mtile * 16 + (ntile >> 2)) * ATILEB;
        float partial = 0.f;
        unsigned hp[4];

        #pragma unroll
        for (int q = 0; q < 2; q++) {               // 2 groups of 4 units
            float4 cold = *(const float4*)(cb + q * 4);
            float co[4] = {cold.x, cold.y, cold.z, cold.w};
            float hv[4];
            #pragma unroll
            for (int v = 0; v < 4; v++) {
                int g4 = q * 16 + v * 4;
                float gi = csm[g4]     + s_beff[jh * 32 + g4];
                float gf = csm[g4 + 1] + s_beff[jh * 32 + g4 + 1];
                float gg = csm[g4 + 2] + s_beff[jh * 32 + g4 + 2];
                float go = csm[g4 + 3] + s_beff[jh * 32 + g4 + 3];
                if (t == 0) {
                    float4 dd = *(const float4*)(d0p + g4);
                    gi += dd.x; gf += dd.y; gg += dd.z; go += dd.w;
                }
                float cn = sigm(gf) * co[v] + sigm(gi) * tanhf(gg);
                hv[v] = sigm(go) * tanhf(cn);
                co[v] = cn;
                partial += hv[v] * s_w127[jh * 8 + q * 4 + v];
            }
            *(float4*)(cb + q * 4) = make_float4(co[0], co[1], co[2], co[3]);
            unsigned lo = (unsigned)__half_as_ushort(__float2half_rn(hv[0]))
                        | ((unsigned)__half_as_ushort(__float2half_rn(hv[1])) << 16);
            unsigned hi = (unsigned)__half_as_ushort(__float2half_rn(hv[2]))
                        | ((unsigned)__half_as_ushort(__float2half_rn(hv[3])) << 16);
            hp[q * 2] = lo; hp[q * 2 + 1] = hi;
        }
        // 8 units = 16 bytes, one aligned uint4 at the swizzled address
        uint32_t bo = (uint32_t)(bl * 128 + (ntile & 3) * 32 + jh * 16);
        *(uint4*)(hT + sw128(bo)) = make_uint4(hp[0], hp[1], hp[2], hp[3]);
        partial += __shfl_xor_sync(0xffffffffu, partial, 1);
        if (jh == 0) d_part[(size_t)t * (64 * BSZ) + ntile * BSZ + b] = partial;
    }
}

// out[b][t] = b_fc[127] + sum over 64 tiles
__global__ void k_reduce(float* __restrict__ out, const float* __restrict__ bfc) {
    int idx = blockIdx.x * 256 + threadIdx.x;
    if (idx >= BSZ * SEQ) return;
    int b = idx / SEQ, t = idx % SEQ;
    float s = bfc[127];
    #pragma unroll 8
    for (int nt = 0; nt < 64; nt++) s += d_part[(size_t)t * (64 * BSZ) + nt * BSZ + b];
    out[idx] = s;
}

extern "C" void kernel_launch(void* const* d_in, const int* in_sizes, int n_in,
                              void* d_out, int out_size) {
    const float* xt   = (const float*)d_in[0];
    const float* hid  = (const float*)d_in[1];
    const float* cell = (const float*)d_in[2];
    const float* Wih  = (const float*)d_in[3];
    const float* Whh  = (const float*)d_in[4];
    const float* bih  = (const float*)d_in[5];
    const float* bhh  = (const float*)d_in[6];
    const float* Wfc  = (const float*)d_in[7];
    const float* bfc  = (const float*)d_in[8];
    float* out = (float*)d_out;

    cudaFuncSetAttribute(k_step, cudaFuncAttributeMaxDynamicSharedMemorySize, SMEM_BYTES);

    k_weff<<<dim3(4, 256), 256>>>(Wih, Whh, Wfc);
    k_state<<<2048, 256>>>(hid, cell);
    k_u0<<<64, 256>>>(xt, hid, Wfc, bfc);
    k_beff<<<16, 256>>>(Wih, bih, bhh, bfc);
    k_d0<<<dim3(32, 128), 128>>>(Wih);

    // 96 dependent steps, PDL chained, 256 CTAs (2 per SM).
    cudaLaunchAttribute at[1];
    at[0].id = cudaLaunchAttributeProgrammaticStreamSerialization;
    at[0].val.programmaticStreamSerializationAllowed = 1;
    cudaLaunchConfig_t cfg = {};
    cfg.gridDim = dim3(64, 4);
    cfg.blockDim = dim3(256);
    cfg.dynamicSmemBytes = SMEM_BYTES;
    cfg.stream = 0;
    cfg.attrs = at;
    cfg.numAttrs = 1;
    for (int t = 0; t < SEQ; t++)
        cudaLaunchKernelEx(&cfg, k_step, t, t & 1, Wfc);

    k_reduce<<<192, 256>>>(out, bfc);
}